// round 15
// baseline (speedup 1.0000x reference)
#include <cuda_runtime.h>
#include <cuda_bf16.h>
#include <cstdint>
#include <cstddef>

#define B_   2
#define P_   8192
#define NNB  24
#define C1_  32
#define C2_  32
#define K_   13
#define A_   12
#define DR_  (C2_*A_)   /* 384 */
#define CA_  (C1_*A_)   /* 384 */
#define BP_  (B_*P_)    /* 16384 */

#define CHUNK 96        /* K cols per chunk (8 c-planes) */
#define CPK   4         /* chunks per k-segment */
#define NKB   6         /* m16n8k16 steps per chunk */
#define TCH   (K_*CPK)  /* 52 chunks */
#define NTHR  512
#define NTILE_N 192

#define SRB   208       /* bf16 tile row stride bytes (conflict-free for LDSM) */

// ---- scratch (device globals; no allocation allowed) ----
__device__ __nv_bfloat16 WTb_g[K_*DR_*CA_];   // [k][dr][ca] bf16 (~3.8MB)
__device__ float md_g[BP_*3];
__device__ float kpo_g[C2_*K_*3];
__device__ float be_g[C2_*A_];

__device__ __forceinline__ uint32_t smem_u32(const void* p) {
    uint32_t a;
    asm("{ .reg .u64 t; cvta.to.shared.u64 t, %1; cvt.u32.u64 %0, t; }" : "=r"(a) : "l"(p));
    return a;
}
__device__ __forceinline__ void cp16(uint32_t dst, const void* src) {
    asm volatile("cp.async.cg.shared.global [%0], [%1], 16;" :: "r"(dst), "l"(src));
}
#define CP_COMMIT() asm volatile("cp.async.commit_group;" ::: "memory")
#define CP_WAIT0()  asm volatile("cp.async.wait_group 0;" ::: "memory")

__device__ __forceinline__ void ldsm_x4(uint32_t& r0, uint32_t& r1, uint32_t& r2, uint32_t& r3,
                                        uint32_t addr) {
    asm volatile("ldmatrix.sync.aligned.m8n8.x4.shared.b16 {%0,%1,%2,%3}, [%4];"
                 : "=r"(r0), "=r"(r1), "=r"(r2), "=r"(r3) : "r"(addr));
}
__device__ __forceinline__ void mma_bf16(float& c0, float& c1, float& c2, float& c3,
                                         uint32_t a0, uint32_t a1, uint32_t a2, uint32_t a3,
                                         uint32_t b0, uint32_t b1) {
    asm volatile("mma.sync.aligned.m16n8k16.row.col.f32.bf16.bf16.f32 "
                 "{%0,%1,%2,%3}, {%4,%5,%6,%7}, {%8,%9}, {%0,%1,%2,%3};"
                 : "+f"(c0), "+f"(c1), "+f"(c2), "+f"(c3)
                 : "r"(a0), "r"(a1), "r"(a2), "r"(a3), "r"(b0), "r"(b1));
}

// ===================== prep kernels =====================
__global__ void build_wt(const float* __restrict__ W,
                         const float* __restrict__ kpw,
                         const int*   __restrict__ idx_map,
                         const int*   __restrict__ tivr,
                         const int*   __restrict__ tir) {
    int u = blockIdx.x * blockDim.x + threadIdx.x;
    const int total2 = K_*DR_*CA_/2;
    for (; u < total2; u += gridDim.x * blockDim.x) {
        int idx = u*2;
        int ca = idx % CA_;
        int t  = idx / CA_;
        int n  = t % DR_;
        int k  = t / DR_;
        int d = n / A_, r = n % A_;
        __nv_bfloat162 h;
        {
            int c = ca / A_, a = ca % A_;
            int j = idx_map[tivr[r*K_ + k]*A_ + tir[r*A_ + a]];
            h.x = __float2bfloat16_rn(W[(d*C1_ + c)*36 + j] * kpw[d*36 + j]);
        }
        {
            int ca2 = ca + 1;
            int c = ca2 / A_, a = ca2 % A_;
            int j = idx_map[tivr[r*K_ + k]*A_ + tir[r*A_ + a]];
            h.y = __float2bfloat16_rn(W[(d*C1_ + c)*36 + j] * kpw[d*36 + j]);
        }
        *(__nv_bfloat162*)(WTb_g + idx) = h;
    }
}

// fused: mean_dir over all blocks + (block 0) kpo/bias_eff tables
__global__ void mean_prep(const int* __restrict__ nbr_idx,
                          const float* __restrict__ verts,
                          const float* __restrict__ kpw,
                          const float* __restrict__ vs,
                          const int*   __restrict__ idx_map,
                          const int*   __restrict__ tivr,
                          const float* __restrict__ bias,
                          const int*   __restrict__ lvl) {
    int bp = blockIdx.x * blockDim.x + threadIdx.x;
    if (bp < BP_) {
        int b = bp >> 13;
        int p = bp & (P_-1);
        const float* vb = verts + b * P_ * 3;
        float vx = vb[p*3+0], vy = vb[p*3+1], vz = vb[p*3+2];
        float sx = 0.f, sy = 0.f, sz = 0.f;
        const int* ni = nbr_idx + bp * NNB;
#pragma unroll 4
        for (int n = 0; n < NNB; n++) {
            int q = ni[n];
            float dx = vb[q*3+0] - vx;
            float dy = vb[q*3+1] - vy;
            float dz = vb[q*3+2] - vz;
            float nrm = sqrtf(dx*dx + dy*dy + dz*dz);
            float sc = 1.0f / fmaxf(nrm, 1e-12f);
            sx += dx*sc; sy += dy*sc; sz += dz*sc;
        }
        const float inv = 1.0f / (float)NNB;
        md_g[bp*3+0] = sx * inv;
        md_g[bp*3+1] = sy * inv;
        md_g[bp*3+2] = sz * inv;
    }
    if (blockIdx.x == 0) {
        for (int t = threadIdx.x; t < C2_*K_; t += blockDim.x) {
            int d = t / K_, k = t % K_;
            float s0 = 0.f, s1 = 0.f, s2 = 0.f;
            for (int a = 0; a < A_; a++) {
                float w = kpw[d*36 + idx_map[k*A_ + a]];
                s0 += w * vs[a*3+0];
                s1 += w * vs[a*3+1];
                s2 += w * vs[a*3+2];
            }
            float nrm = sqrtf(s0*s0 + s1*s1 + s2*s2);
            float inv = 1.0f / fmaxf(nrm, 1e-12f);
            kpo_g[t*3+0] = s0*inv;
            kpo_g[t*3+1] = s1*inv;
            kpo_g[t*3+2] = s2*inv;
        }
        for (int t = threadIdx.x; t < C2_*A_; t += blockDim.x) {
            int d = t / A_, r = t % A_;
            float s = 0.f;
            for (int k = 0; k < K_; k++)
                s += bias[d*5 + lvl[tivr[r*K_ + k]]];
            be_g[t] = s;
        }
    }
}

// ===================== main bf16 mma kernel (fused fp32->bf16 convert) =====
// 512 thr, 1 CTA/SM. Warp grid 4m x 4n (warp tile 32x48), CTA tile 128x192,
// grid (2,128). A staged as fp32 via cp.async (single buffer, 400B rows),
// converted in-kernel to the bf16 A tile (single buffer, 208B rows). B bf16
// double-buffered. Pipeline: wait -> sync -> convert -> sync -> issue(t+1)
// -> mma(t) -> fold.
// smem (floats):
//   A32 [128][100] @0       (12800)
//   A16 [128][52]  @12800   (6656)   bf16 tile viewed as floats
//   B   [2][192][52] @19456 (19968)
//   MD  @39424 (384)  KPO @39808 (624)  BE @40432 (192)
#define OFF_A32 0
#define OFF_A16 12800
#define OFF_B   19456
#define OFF_MD  39424
#define OFF_KPO 39808
#define OFF_BE  40432
#define SMEM_FLOATS 40624
#define SMEM_BYTES (SMEM_FLOATS*4)   /* 162496 B */
#define B_STG_BY (192*SRB)           /* 39936 */

__global__ __launch_bounds__(NTHR, 1) void equi_mma(const float* __restrict__ fm,
                                                    float* __restrict__ out) {
    extern __shared__ float s[];
    float* A32 = s + OFF_A32;
    float* MD  = s + OFF_MD;
    float* KPO = s + OFF_KPO;
    float* BE  = s + OFF_BE;
    const uint32_t sS   = smem_u32(s);
    const uint32_t sA32 = sS;
    const uint32_t sA16 = sS + OFF_A16*4;
    const uint32_t sB   = sS + OFF_B*4;

    const int tid  = threadIdx.x;
    const int wid  = tid >> 5;          // 0..15
    const int lane = tid & 31;
    const int gid  = lane >> 2;
    const int tig  = lane & 3;

    const int Ntile = blockIdx.x;        // 0..1
    const int Mtile = blockIdx.y;        // 0..127
    const int b  = Mtile >> 6;
    const int p0 = (Mtile & 63) << 7;
    const int n0 = Ntile * NTILE_N;
    const int d0 = Ntile * 16;

    const int m0w = (wid & 3) * 32;      // warp tile 32m x 48n
    const int n0w = (wid >> 2) * 48;     // 0,48,96,144

    for (int i = tid; i < 128*3; i += NTHR) MD[i]  = md_g[(size_t)Mtile*128*3 + i];
    for (int i = tid; i < 16*K_*3; i += NTHR) KPO[i] = kpo_g[d0*(K_*3) + i];
    if (tid < NTILE_N) BE[tid] = be_g[d0*A_ + tid];

    float acc[2][6][4];
#pragma unroll
    for (int mt = 0; mt < 2; mt++)
#pragma unroll
        for (int nt = 0; nt < 6; nt++)
#pragma unroll
            for (int q = 0; q < 4; q++) acc[mt][nt][q] = 0.f;

    // ---- A fp32 copy offsets: 3072 cp16 -> 6/thread ----
    // o = tid + i*512: row = o/24, q = o%24, cq = q/3 (c-plane), i3 = q%3
    uint32_t aDst[6], aSrcOff[6];
    int      aPlaneK[6];
#pragma unroll
    for (int i = 0; i < 6; i++) {
        int o   = tid + i*NTHR;
        int row = o / 24, q = o - row*24;
        int cq  = q / 3,  i3 = q - cq*3;
        aDst[i]    = sA32 + (uint32_t)(row*400 + q*16);
        aSrcOff[i] = (uint32_t)((p0 + row)*12 + i3*4);      // float index
        aPlaneK[i] = cq * K_;                               // + j*8*K_ + k at use
    }
    // ---- B copy offsets: 2304 cp16 -> 4/thread + half ----
    uint32_t bS[5], bG[5];
#pragma unroll
    for (int i = 0; i < 5; i++) {
        int o = tid + i*NTHR;
        int row = o / 12, q = o - row*12;
        bS[i] = (uint32_t)(row*SRB + q*16);
        bG[i] = (uint32_t)(row*768 + q*16);
    }
    const float* fm_b    = fm + (size_t)b * C1_ * K_ * P_ * A_;
    const char*  wtb_base = (const char*)WTb_g + (size_t)n0*768;

    const uint32_t lmA = sA16 + (uint32_t)((m0w + (lane & 15))*SRB + ((lane & 16) ? 16 : 0));
    const uint32_t lmB = (uint32_t)((n0w + (lane & 15))*SRB + ((lane & 16) ? 16 : 0));

    // convert mapping: p = tid&127, seg = tid>>7 (conflict-free LDS + STS)
    const int cvP = tid & 127;
    const int cvS = tid >> 7;

    auto issue_copies = [&](int t) {
        int k = t >> 2, j = t & 3;
        int jk = j*8*K_ + k;
#pragma unroll
        for (int i = 0; i < 6; i++) {
            const float* src = fm_b + (size_t)(aPlaneK[i] + jk)*(P_*12) + aSrcOff[i];
            cp16(aDst[i], src);
        }
        uint32_t dstB = sB + (uint32_t)((t & 1))*B_STG_BY;
        const char* bsrc = wtb_base + (size_t)k*(DR_*CA_*2) + j*192;
#pragma unroll
        for (int i = 0; i < 4; i++) cp16(dstB + bS[i], bsrc + bG[i]);
        if (tid < 256) cp16(dstB + bS[4], bsrc + bG[4]);
    };

    issue_copies(0); CP_COMMIT();

    for (int t = 0; t < TCH; t++) {
        const int k  = t >> 2;
        const int j  = t & 3;

        CP_WAIT0();            // A32(t) + B(t&1) landed
        __syncthreads();       // visible; A16 readers of t-1 done

        // ---- convert A32 -> A16 (bit-identical __float2bfloat16_rn) ----
        {
            const float* srcp = A32 + cvP*100 + cvS*24;
            uint32_t u[12];
#pragma unroll
            for (int i = 0; i < 6; i++) {
                float4 v = *(const float4*)(srcp + i*4);
                __nv_bfloat162 h0, h1;
                h0.x = __float2bfloat16_rn(v.x);
                h0.y = __float2bfloat16_rn(v.y);
                h1.x = __float2bfloat16_rn(v.z);
                h1.y = __float2bfloat16_rn(v.w);
                u[2*i]   = *(uint32_t*)&h0;
                u[2*i+1] = *(uint32_t*)&h1;
            }
            char* dstp = (char*)s + OFF_A16*4 + cvP*SRB + cvS*48;
#pragma unroll
            for (int w = 0; w < 3; w++)
                *(uint4*)(dstp + w*16) = make_uint4(u[4*w], u[4*w+1], u[4*w+2], u[4*w+3]);
        }
        __syncthreads();       // convert done (A32 free, A16 ready)

        if (t + 1 < TCH) { issue_copies(t + 1); CP_COMMIT(); }

        const uint32_t Bb = sB + (uint32_t)(t & 1)*B_STG_BY;
#pragma unroll
        for (int kb = 0; kb < NKB; kb++) {
            const uint32_t co = (uint32_t)kb*32;
            uint32_t b0[6], b1[6];
#pragma unroll
            for (int ntp = 0; ntp < 3; ntp++) {
                uint32_t r0, r1, r2, r3;
                ldsm_x4(r0, r1, r2, r3, Bb + lmB + (uint32_t)(ntp*16*SRB) + co);
                b0[2*ntp]   = r0; b1[2*ntp]   = r2;
                b0[2*ntp+1] = r1; b1[2*ntp+1] = r3;
            }
#pragma unroll
            for (int mt = 0; mt < 2; mt++) {
                uint32_t a0, a1, a2, a3;
                ldsm_x4(a0, a1, a2, a3, lmA + (uint32_t)(mt*16*SRB) + co);
#pragma unroll
                for (int nt = 0; nt < 6; nt++)
                    mma_bf16(acc[mt][nt][0], acc[mt][nt][1], acc[mt][nt][2], acc[mt][nt][3],
                             a0, a1, a2, a3, b0[nt], b1[nt]);
            }
        }

        if (j == CPK-1) {
            // fold: out (+)= pw * acc  (CTA-disjoint; L2-resident)
#pragma unroll
            for (int mt = 0; mt < 2; mt++) {
                int r0 = m0w + mt*16 + gid;
                int r1 = r0 + 8;
                float m0x = MD[r0*3+0], m0y = MD[r0*3+1], m0z = MD[r0*3+2];
                float m1x = MD[r1*3+0], m1y = MD[r1*3+1], m1z = MD[r1*3+2];
#pragma unroll
                for (int nt = 0; nt < 6; nt++) {
                    int n  = n0w + nt*8 + tig*2;
                    int dl = n / 12;
                    int rr = n - dl*12;
                    const float* kp = KPO + (dl*K_ + k)*3;
                    float pw0 = fmaxf(m0x*kp[0] + m0y*kp[1] + m0z*kp[2], 0.f);
                    float pw1 = fmaxf(m1x*kp[0] + m1y*kp[1] + m1z*kp[2], 0.f);
                    float* o0 = out + ((size_t)(b*C2_ + d0 + dl)*P_ + p0 + r0)*A_ + rr;
                    float* o1 = out + ((size_t)(b*C2_ + d0 + dl)*P_ + p0 + r1)*A_ + rr;
                    if (k == 0) {
                        *(float2*)o0 = make_float2(pw0*acc[mt][nt][0], pw0*acc[mt][nt][1]);
                        *(float2*)o1 = make_float2(pw1*acc[mt][nt][2], pw1*acc[mt][nt][3]);
                    } else if (k == K_-1) {
                        float2 c0 = *(float2*)o0, c1 = *(float2*)o1;
                        float be0 = BE[n], be1 = BE[n+1];
                        c0.x = fmaxf(fmaf(pw0, acc[mt][nt][0], c0.x) + be0, 0.f);
                        c0.y = fmaxf(fmaf(pw0, acc[mt][nt][1], c0.y) + be1, 0.f);
                        c1.x = fmaxf(fmaf(pw1, acc[mt][nt][2], c1.x) + be0, 0.f);
                        c1.y = fmaxf(fmaf(pw1, acc[mt][nt][3], c1.y) + be1, 0.f);
                        *(float2*)o0 = c0;
                        *(float2*)o1 = c1;
                    } else {
                        float2 c0 = *(float2*)o0, c1 = *(float2*)o1;
                        c0.x = fmaf(pw0, acc[mt][nt][0], c0.x);
                        c0.y = fmaf(pw0, acc[mt][nt][1], c0.y);
                        c1.x = fmaf(pw1, acc[mt][nt][2], c1.x);
                        c1.y = fmaf(pw1, acc[mt][nt][3], c1.y);
                        *(float2*)o0 = c0;
                        *(float2*)o1 = c1;
                    }
                    acc[mt][nt][0] = 0.f; acc[mt][nt][1] = 0.f;
                    acc[mt][nt][2] = 0.f; acc[mt][nt][3] = 0.f;
                }
            }
        }
    }
}

// ---------------------------------------------------------------------------
extern "C" void kernel_launch(void* const* d_in, const int* in_sizes, int n_in,
                              void* d_out, int out_size) {
    const int*   nbr     = (const int*)  d_in[0];
    const float* verts   = (const float*)d_in[1];
    const float* fm      = (const float*)d_in[2];
    const float* W       = (const float*)d_in[3];
    const float* bias    = (const float*)d_in[4];
    const float* kpw     = (const float*)d_in[5];
    const float* vs      = (const float*)d_in[6];
    const int*   idx_map = (const int*)  d_in[7];
    const int*   tivr    = (const int*)  d_in[8];
    const int*   tir     = (const int*)  d_in[9];
    const int*   lvl     = (const int*)  d_in[10];
    float* out = (float*)d_out;

    static int smem_set = 0;
    if (!smem_set) {
        cudaFuncSetAttribute(equi_mma, cudaFuncAttributeMaxDynamicSharedMemorySize, SMEM_BYTES);
        smem_set = 1;
    }

    build_wt<<<256, 256>>>(W, kpw, idx_map, tivr, tir);                           // launch 0
    mean_prep<<<BP_/256, 256>>>(nbr, verts, kpw, vs, idx_map, tivr, bias, lvl);   // launch 1
    dim3 grid(2, 128);
    equi_mma<<<grid, NTHR, SMEM_BYTES>>>(fm, out);                                // launch 2
}

// round 16
// speedup vs baseline: 1.2121x; 1.2121x over previous
#include <cuda_runtime.h>
#include <cuda_bf16.h>
#include <cstdint>
#include <cstddef>

#define B_   2
#define P_   8192
#define NNB  24
#define C1_  32
#define C2_  32
#define K_   13
#define A_   12
#define DR_  (C2_*A_)   /* 384 */
#define CA_  (C1_*A_)   /* 384 */
#define BP_  (B_*P_)    /* 16384 */

#define CHUNK 96        /* K cols per stage (8 c-planes) */
#define CPK   4         /* chunks per k-segment */
#define NKB   6         /* m16n8k16 steps per chunk */
#define TCH   (K_*CPK)  /* 52 chunks */
#define NSTG  2
#define NTHR  256
#define NTILE_N 96

#define SRB   208                        /* smem row stride bytes (conflict-free) */
#define STG_A_BY  (128*SRB)              /* 26624 */
#define STG_B_BY  (NTILE_N*SRB)          /* 19968 */
#define STG_BY    (STG_A_BY + STG_B_BY)  /* 46592 */

// ---- scratch (device globals; no allocation allowed) ----
__device__ __nv_bfloat16 fmbf_g[(size_t)B_*K_*CPK*P_*CHUNK];  // [b][k][j][p][96] (~164MB)
__device__ __nv_bfloat16 WTb_g[K_*DR_*CA_];                   // [k][dr][ca] bf16 (~3.8MB)
__device__ float md_g[BP_*3];
__device__ float kpo_g[C2_*K_*3];
__device__ float be_g[C2_*A_];

__device__ __forceinline__ uint32_t smem_u32(const void* p) {
    uint32_t a;
    asm("{ .reg .u64 t; cvta.to.shared.u64 t, %1; cvt.u32.u64 %0, t; }" : "=r"(a) : "l"(p));
    return a;
}
__device__ __forceinline__ void cp16(uint32_t dst, const void* src) {
    asm volatile("cp.async.cg.shared.global [%0], [%1], 16;" :: "r"(dst), "l"(src));
}
#define CP_COMMIT() asm volatile("cp.async.commit_group;" ::: "memory")
#define CP_WAIT0()  asm volatile("cp.async.wait_group 0;" ::: "memory")

__device__ __forceinline__ void ldsm_x4(uint32_t& r0, uint32_t& r1, uint32_t& r2, uint32_t& r3,
                                        uint32_t addr) {
    asm volatile("ldmatrix.sync.aligned.m8n8.x4.shared.b16 {%0,%1,%2,%3}, [%4];"
                 : "=r"(r0), "=r"(r1), "=r"(r2), "=r"(r3) : "r"(addr));
}
__device__ __forceinline__ void mma_bf16(float& c0, float& c1, float& c2, float& c3,
                                         uint32_t a0, uint32_t a1, uint32_t a2, uint32_t a3,
                                         uint32_t b0, uint32_t b1) {
    asm volatile("mma.sync.aligned.m16n8k16.row.col.f32.bf16.bf16.f32 "
                 "{%0,%1,%2,%3}, {%4,%5,%6,%7}, {%8,%9}, {%0,%1,%2,%3};"
                 : "+f"(c0), "+f"(c1), "+f"(c2), "+f"(c3)
                 : "r"(a0), "r"(a1), "r"(a2), "r"(a3), "r"(b0), "r"(b1));
}

// ===================== prep kernels =====================
__global__ void build_wt(const float* __restrict__ W,
                         const float* __restrict__ kpw,
                         const int*   __restrict__ idx_map,
                         const int*   __restrict__ tivr,
                         const int*   __restrict__ tir) {
    int u = blockIdx.x * blockDim.x + threadIdx.x;
    const int total2 = K_*DR_*CA_/2;
    for (; u < total2; u += gridDim.x * blockDim.x) {
        int idx = u*2;
        int ca = idx % CA_;
        int t  = idx / CA_;
        int n  = t % DR_;
        int k  = t / DR_;
        int d = n / A_, r = n % A_;
        __nv_bfloat162 h;
        {
            int c = ca / A_, a = ca % A_;
            int j = idx_map[tivr[r*K_ + k]*A_ + tir[r*A_ + a]];
            h.x = __float2bfloat16_rn(W[(d*C1_ + c)*36 + j] * kpw[d*36 + j]);
        }
        {
            int ca2 = ca + 1;
            int c = ca2 / A_, a = ca2 % A_;
            int j = idx_map[tivr[r*K_ + k]*A_ + tir[r*A_ + a]];
            h.y = __float2bfloat16_rn(W[(d*C1_ + c)*36 + j] * kpw[d*36 + j]);
        }
        *(__nv_bfloat162*)(WTb_g + idx) = h;
    }
}

// conv_fm v3: one thread = one float4 (4 consecutive a-values of one c-plane
// row) -> 4x cvt -> one 8B store. Output rows contiguous (24 thr = 192B row).
// Element-wise conversion identical to before -> bit-identical fmbf.
#define TOT4 ((size_t)B_*K_*CPK*P_*24)
__global__ __launch_bounds__(256) void conv_fm(const float* __restrict__ fm) {
    size_t o = (size_t)blockIdx.x * blockDim.x + threadIdx.x;
    if (o >= TOT4) return;
    int    q    = (int)(o % 24);         // c*3 + aq
    size_t rest = o / 24;
    int    p    = (int)(rest & (P_-1));
    int    bkj  = (int)(rest >> 13);     // (b*K_+k)*CPK + j
    int    j    = bkj & 3;
    int    bk   = bkj >> 2;
    int    k    = bk % K_;
    int    b    = bk / K_;
    int    c    = q / 3, aq = q - c*3;

    const float4 v = *(const float4*)(fm +
        (((size_t)(b*C1_ + j*8 + c)*K_ + k)*P_ + p)*A_ + aq*4);
    __nv_bfloat162 h0, h1;
    h0.x = __float2bfloat16_rn(v.x);
    h0.y = __float2bfloat16_rn(v.y);
    h1.x = __float2bfloat16_rn(v.z);
    h1.y = __float2bfloat16_rn(v.w);
    uint2 w = make_uint2(*(uint32_t*)&h0, *(uint32_t*)&h1);
    *(uint2*)((char*)fmbf_g + ((size_t)bkj*P_ + p)*192 + c*24 + aq*8) = w;
}

// fused: mean_dir over all blocks + (block 0) kpo/bias_eff tables
__global__ void mean_prep(const int* __restrict__ nbr_idx,
                          const float* __restrict__ verts,
                          const float* __restrict__ kpw,
                          const float* __restrict__ vs,
                          const int*   __restrict__ idx_map,
                          const int*   __restrict__ tivr,
                          const float* __restrict__ bias,
                          const int*   __restrict__ lvl) {
    int bp = blockIdx.x * blockDim.x + threadIdx.x;
    if (bp < BP_) {
        int b = bp >> 13;
        int p = bp & (P_-1);
        const float* vb = verts + b * P_ * 3;
        float vx = vb[p*3+0], vy = vb[p*3+1], vz = vb[p*3+2];
        float sx = 0.f, sy = 0.f, sz = 0.f;
        const int* ni = nbr_idx + bp * NNB;
#pragma unroll 4
        for (int n = 0; n < NNB; n++) {
            int q = ni[n];
            float dx = vb[q*3+0] - vx;
            float dy = vb[q*3+1] - vy;
            float dz = vb[q*3+2] - vz;
            float nrm = sqrtf(dx*dx + dy*dy + dz*dz);
            float sc = 1.0f / fmaxf(nrm, 1e-12f);
            sx += dx*sc; sy += dy*sc; sz += dz*sc;
        }
        const float inv = 1.0f / (float)NNB;
        md_g[bp*3+0] = sx * inv;
        md_g[bp*3+1] = sy * inv;
        md_g[bp*3+2] = sz * inv;
    }
    if (blockIdx.x == 0) {
        for (int t = threadIdx.x; t < C2_*K_; t += blockDim.x) {
            int d = t / K_, k = t % K_;
            float s0 = 0.f, s1 = 0.f, s2 = 0.f;
            for (int a = 0; a < A_; a++) {
                float w = kpw[d*36 + idx_map[k*A_ + a]];
                s0 += w * vs[a*3+0];
                s1 += w * vs[a*3+1];
                s2 += w * vs[a*3+2];
            }
            float nrm = sqrtf(s0*s0 + s1*s1 + s2*s2);
            float inv = 1.0f / fmaxf(nrm, 1e-12f);
            kpo_g[t*3+0] = s0*inv;
            kpo_g[t*3+1] = s1*inv;
            kpo_g[t*3+2] = s2*inv;
        }
        for (int t = threadIdx.x; t < C2_*A_; t += blockDim.x) {
            int d = t / A_, r = t % A_;
            float s = 0.f;
            for (int k = 0; k < K_; k++)
                s += bias[d*5 + lvl[tivr[r*K_ + k]]];
            be_g[t] = s;
        }
    }
}

// ===================== main bf16 mma kernel (champion, verbatim) ===========
// 256 thr, warp grid 4m x 2n (warp tile 32x48), CTA tile 128x96, grid (4,128).
// CHUNK=96, 2-stage ring, issue(t+1) before compute(t), 1 sync/chunk,
// acc in regs, per-k fold -> global out (CTA-disjoint, L2-resident).
#define OFF_MD  23296
#define OFF_KPO 23680
#define OFF_BE  23992
#define SMEM_FLOATS 24088
#define SMEM_BYTES (SMEM_FLOATS*4)   /* 96352 B -> 2 CTAs/SM */

__global__ __launch_bounds__(NTHR, 2) void equi_mma(float* __restrict__ out) {
    extern __shared__ float s[];
    float* MD  = s + OFF_MD;
    float* KPO = s + OFF_KPO;
    float* BE  = s + OFF_BE;
    const uint32_t sS = smem_u32(s);

    const int tid  = threadIdx.x;
    const int wid  = tid >> 5;
    const int lane = tid & 31;
    const int gid  = lane >> 2;
    const int tig  = lane & 3;

    const int Ntile = blockIdx.x;        // 0..3
    const int Mtile = blockIdx.y;        // 0..127
    const int b  = Mtile >> 6;
    const int p0 = (Mtile & 63) << 7;
    const int n0 = Ntile * NTILE_N;
    const int d0 = Ntile * 8;

    const int m0w = (wid & 3) * 32;      // warp tile 32m x 48n
    const int n0w = (wid >> 2) * 48;

    for (int i = tid; i < 128*3; i += NTHR) MD[i]  = md_g[(size_t)Mtile*128*3 + i];
    for (int i = tid; i < 8*K_*3; i += NTHR) KPO[i] = kpo_g[d0*(K_*3) + i];
    if (tid < NTILE_N) BE[tid] = be_g[d0*A_ + tid];

    float acc[2][6][4];
#pragma unroll
    for (int mt = 0; mt < 2; mt++)
#pragma unroll
        for (int nt = 0; nt < 6; nt++)
#pragma unroll
            for (int q = 0; q < 4; q++) acc[mt][nt][q] = 0.f;

    // ---- precomputed copy offsets ----
    // A: 128 rows x 12 x 16B = 1536 cp16 -> 6/thread
    uint32_t aS[6], aG[6];
#pragma unroll
    for (int i = 0; i < 6; i++) {
        int o = tid + i*NTHR;
        int row = o / 12, q = o - row*12;
        aS[i] = (uint32_t)(row*SRB + q*16);
        aG[i] = (uint32_t)(row*192 + q*16);
    }
    // B: 96 rows x 12 x 16B = 1152 cp16 -> 4/thread + half
    uint32_t bS[5], bG[5];
#pragma unroll
    for (int i = 0; i < 5; i++) {
        int o = tid + i*NTHR;
        int row = o / 12, q = o - row*12;
        bS[i] = (uint32_t)(row*SRB + q*16);
        bG[i] = (uint32_t)(row*768 + q*16);
    }
    const char* fm_base  = (const char*)fmbf_g + (size_t)b*(K_*CPK*P_*192) + (size_t)p0*192;
    const char* wtb_base = (const char*)WTb_g + (size_t)n0*768;

    const uint32_t lmA = (uint32_t)((m0w + (lane & 15))*SRB + ((lane & 16) ? 16 : 0));
    const uint32_t lmB = (uint32_t)((n0w + (lane & 15))*SRB + ((lane & 16) ? 16 : 0));

    auto issue_copies = [&](int t) {
        uint32_t dstA = sS + (uint32_t)(t & 1)*STG_BY;
        uint32_t dstB = dstA + STG_A_BY;
        const char* asrc = fm_base + (size_t)t*(P_*192);
#pragma unroll
        for (int i = 0; i < 6; i++) cp16(dstA + aS[i], asrc + aG[i]);
        int k = t >> 2, j = t & 3;
        const char* bsrc = wtb_base + (size_t)k*(DR_*CA_*2) + j*192;
#pragma unroll
        for (int i = 0; i < 4; i++) cp16(dstB + bS[i], bsrc + bG[i]);
        if (tid < 128) cp16(dstB + bS[4], bsrc + bG[4]);
    };

    issue_copies(0); CP_COMMIT();

    for (int t = 0; t < TCH; t++) {
        const int k  = t >> 2;
        const int j  = t & 3;

        CP_WAIT0();            // chunk t landed
        __syncthreads();       // data visible; other buffer's readers done

        if (t + 1 < TCH) { issue_copies(t + 1); CP_COMMIT(); }

        const uint32_t Ab = sS + (uint32_t)(t & 1)*STG_BY;
        const uint32_t Bb = Ab + STG_A_BY;
#pragma unroll
        for (int kb = 0; kb < NKB; kb++) {
            const uint32_t co = (uint32_t)kb*32;
            uint32_t b0[6], b1[6];
#pragma unroll
            for (int ntp = 0; ntp < 3; ntp++) {
                uint32_t r0, r1, r2, r3;
                ldsm_x4(r0, r1, r2, r3, Bb + lmB + (uint32_t)(ntp*16*SRB) + co);
                b0[2*ntp]   = r0; b1[2*ntp]   = r2;
                b0[2*ntp+1] = r1; b1[2*ntp+1] = r3;
            }
#pragma unroll
            for (int mt = 0; mt < 2; mt++) {
                uint32_t a0, a1, a2, a3;
                ldsm_x4(a0, a1, a2, a3, Ab + lmA + (uint32_t)(mt*16*SRB) + co);
#pragma unroll
                for (int nt = 0; nt < 6; nt++)
                    mma_bf16(acc[mt][nt][0], acc[mt][nt][1], acc[mt][nt][2], acc[mt][nt][3],
                             a0, a1, a2, a3, b0[nt], b1[nt]);
            }
        }

        if (j == CPK-1) {
            // fold: out (+)= pw * acc  (CTA-disjoint; L2-resident)
#pragma unroll
            for (int mt = 0; mt < 2; mt++) {
                int r0 = m0w + mt*16 + gid;
                int r1 = r0 + 8;
                float m0x = MD[r0*3+0], m0y = MD[r0*3+1], m0z = MD[r0*3+2];
                float m1x = MD[r1*3+0], m1y = MD[r1*3+1], m1z = MD[r1*3+2];
#pragma unroll
                for (int nt = 0; nt < 6; nt++) {
                    int n  = n0w + nt*8 + tig*2;
                    int dl = n / 12;
                    int rr = n - dl*12;
                    const float* kp = KPO + (dl*K_ + k)*3;
                    float pw0 = fmaxf(m0x*kp[0] + m0y*kp[1] + m0z*kp[2], 0.f);
                    float pw1 = fmaxf(m1x*kp[0] + m1y*kp[1] + m1z*kp[2], 0.f);
                    float* o0 = out + ((size_t)(b*C2_ + d0 + dl)*P_ + p0 + r0)*A_ + rr;
                    float* o1 = out + ((size_t)(b*C2_ + d0 + dl)*P_ + p0 + r1)*A_ + rr;
                    if (k == 0) {
                        *(float2*)o0 = make_float2(pw0*acc[mt][nt][0], pw0*acc[mt][nt][1]);
                        *(float2*)o1 = make_float2(pw1*acc[mt][nt][2], pw1*acc[mt][nt][3]);
                    } else if (k == K_-1) {
                        float2 c0 = *(float2*)o0, c1 = *(float2*)o1;
                        float be0 = BE[n], be1 = BE[n+1];
                        c0.x = fmaxf(fmaf(pw0, acc[mt][nt][0], c0.x) + be0, 0.f);
                        c0.y = fmaxf(fmaf(pw0, acc[mt][nt][1], c0.y) + be1, 0.f);
                        c1.x = fmaxf(fmaf(pw1, acc[mt][nt][2], c1.x) + be0, 0.f);
                        c1.y = fmaxf(fmaf(pw1, acc[mt][nt][3], c1.y) + be1, 0.f);
                        *(float2*)o0 = c0;
                        *(float2*)o1 = c1;
                    } else {
                        float2 c0 = *(float2*)o0, c1 = *(float2*)o1;
                        c0.x = fmaf(pw0, acc[mt][nt][0], c0.x);
                        c0.y = fmaf(pw0, acc[mt][nt][1], c0.y);
                        c1.x = fmaf(pw1, acc[mt][nt][2], c1.x);
                        c1.y = fmaf(pw1, acc[mt][nt][3], c1.y);
                        *(float2*)o0 = c0;
                        *(float2*)o1 = c1;
                    }
                    acc[mt][nt][0] = 0.f; acc[mt][nt][1] = 0.f;
                    acc[mt][nt][2] = 0.f; acc[mt][nt][3] = 0.f;
                }
            }
        }
    }
}

// ---------------------------------------------------------------------------
extern "C" void kernel_launch(void* const* d_in, const int* in_sizes, int n_in,
                              void* d_out, int out_size) {
    const int*   nbr     = (const int*)  d_in[0];
    const float* verts   = (const float*)d_in[1];
    const float* fm      = (const float*)d_in[2];
    const float* W       = (const float*)d_in[3];
    const float* bias    = (const float*)d_in[4];
    const float* kpw     = (const float*)d_in[5];
    const float* vs      = (const float*)d_in[6];
    const int*   idx_map = (const int*)  d_in[7];
    const int*   tivr    = (const int*)  d_in[8];
    const int*   tir     = (const int*)  d_in[9];
    const int*   lvl     = (const int*)  d_in[10];
    float* out = (float*)d_out;

    static int smem_set = 0;
    if (!smem_set) {
        cudaFuncSetAttribute(equi_mma, cudaFuncAttributeMaxDynamicSharedMemorySize, SMEM_BYTES);
        smem_set = 1;
    }

    build_wt<<<256, 256>>>(W, kpw, idx_map, tivr, tir);                           // launch 0
    conv_fm<<<(int)((TOT4 + 255)/256), 256>>>(fm);                                // launch 1
    mean_prep<<<BP_/256, 256>>>(nbr, verts, kpw, vs, idx_map, tivr, bias, lvl);   // launch 2
    dim3 grid(4, 128);
    equi_mma<<<grid, NTHR, SMEM_BYTES>>>(out);                                    // launch 3
}

// round 17
// speedup vs baseline: 1.2265x; 1.0119x over previous
#include <cuda_runtime.h>
#include <cuda_bf16.h>
#include <cstdint>
#include <cstddef>

#define B_   2
#define P_   8192
#define NNB  24
#define C1_  32
#define C2_  32
#define K_   13
#define A_   12
#define DR_  (C2_*A_)   /* 384 */
#define CA_  (C1_*A_)   /* 384 */
#define BP_  (B_*P_)    /* 16384 */

#define CHUNK 96        /* K cols per stage (8 c-planes) */
#define CPK   4         /* chunks per k-segment */
#define NKB   6         /* m16n8k16 steps per chunk */
#define TCH   (K_*CPK)  /* 52 chunks */
#define NSTG  2
#define NTHR  256
#define NTILE_N 96

#define SRB   208                        /* smem row stride bytes (conflict-free) */
#define STG_A_BY  (128*SRB)              /* 26624 */
#define STG_B_BY  (NTILE_N*SRB)          /* 19968 */
#define STG_BY    (STG_A_BY + STG_B_BY)  /* 46592 */

// ---- scratch (device globals; no allocation allowed) ----
__device__ __nv_bfloat16 fmbf_g[(size_t)B_*K_*CPK*P_*CHUNK];  // [b][k][j][p][96] (~164MB)
__device__ __nv_bfloat16 WTb_g[K_*DR_*CA_];                   // [k][dr][ca] bf16 (~3.8MB)
__device__ float md_g[BP_*3];
__device__ float kpo_g[C2_*K_*3];
__device__ float be_g[C2_*A_];

__device__ __forceinline__ uint32_t smem_u32(const void* p) {
    uint32_t a;
    asm("{ .reg .u64 t; cvta.to.shared.u64 t, %1; cvt.u32.u64 %0, t; }" : "=r"(a) : "l"(p));
    return a;
}
__device__ __forceinline__ void cp16(uint32_t dst, const void* src) {
    asm volatile("cp.async.cg.shared.global [%0], [%1], 16;" :: "r"(dst), "l"(src));
}
#define CP_COMMIT() asm volatile("cp.async.commit_group;" ::: "memory")
#define CP_WAIT0()  asm volatile("cp.async.wait_group 0;" ::: "memory")

__device__ __forceinline__ void ldsm_x4(uint32_t& r0, uint32_t& r1, uint32_t& r2, uint32_t& r3,
                                        uint32_t addr) {
    asm volatile("ldmatrix.sync.aligned.m8n8.x4.shared.b16 {%0,%1,%2,%3}, [%4];"
                 : "=r"(r0), "=r"(r1), "=r"(r2), "=r"(r3) : "r"(addr));
}
__device__ __forceinline__ void mma_bf16(float& c0, float& c1, float& c2, float& c3,
                                         uint32_t a0, uint32_t a1, uint32_t a2, uint32_t a3,
                                         uint32_t b0, uint32_t b1) {
    asm volatile("mma.sync.aligned.m16n8k16.row.col.f32.bf16.bf16.f32 "
                 "{%0,%1,%2,%3}, {%4,%5,%6,%7}, {%8,%9}, {%0,%1,%2,%3};"
                 : "+f"(c0), "+f"(c1), "+f"(c2), "+f"(c3)
                 : "r"(a0), "r"(a1), "r"(a2), "r"(a3), "r"(b0), "r"(b1));
}

// ===================== fused prep kernel =====================
// Block partition:
//   [0, CONV_BLKS)               conv: fm fp32 -> fmbf bf16 (2 elems/thread)
//   [CONV_BLKS, CONV_BLKS+64)    mean_dir (+ tables on first block)
//   [CONV_BLKS+64, +BUILD_BLKS)  build_wt
#define TOT4       ((size_t)B_*K_*CPK*P_*24)          /* 20,447,232 */
#define CONV_BLKS  ((int)(TOT4/512))                  /* 39,936 */
#define BUILD_TOT2 (K_*DR_*CA_/2)                     /* 958,464 */
#define BUILD_BLKS (BUILD_TOT2/256)                   /* 3,744 */
#define PREP_BLKS  (CONV_BLKS + 64 + BUILD_BLKS)

__global__ __launch_bounds__(256) void prep_all(
    const float* __restrict__ fm,
    const int*   __restrict__ nbr_idx,
    const float* __restrict__ verts,
    const float* __restrict__ W,
    const float* __restrict__ kpw,
    const float* __restrict__ vs,
    const int*   __restrict__ idx_map,
    const int*   __restrict__ tivr,
    const int*   __restrict__ tir,
    const float* __restrict__ bias,
    const int*   __restrict__ lvl)
{
    const int bid = blockIdx.x;
    const int tid = threadIdx.x;

    if (bid < CONV_BLKS) {
        // ---- conv: identical element math to conv_fm v3 (bit-identical) ----
#pragma unroll
        for (int i = 0; i < 2; i++) {
            size_t o = (size_t)bid*512 + tid + i*256;
            int    q    = (int)(o % 24);         // c*3 + aq
            size_t rest = o / 24;
            int    p    = (int)(rest & (P_-1));
            int    bkj  = (int)(rest >> 13);     // (b*K_+k)*CPK + j
            int    j    = bkj & 3;
            int    bk   = bkj >> 2;
            int    k    = bk % K_;
            int    b    = bk / K_;
            int    c    = q / 3, aq = q - c*3;

            const float4 v = *(const float4*)(fm +
                (((size_t)(b*C1_ + j*8 + c)*K_ + k)*P_ + p)*A_ + aq*4);
            __nv_bfloat162 h0, h1;
            h0.x = __float2bfloat16_rn(v.x);
            h0.y = __float2bfloat16_rn(v.y);
            h1.x = __float2bfloat16_rn(v.z);
            h1.y = __float2bfloat16_rn(v.w);
            uint2 w = make_uint2(*(uint32_t*)&h0, *(uint32_t*)&h1);
            *(uint2*)((char*)fmbf_g + ((size_t)bkj*P_ + p)*192 + c*24 + aq*8) = w;
        }
    } else if (bid < CONV_BLKS + 64) {
        // ---- mean_dir ----
        int bp = (bid - CONV_BLKS)*256 + tid;
        {
            int b = bp >> 13;
            int p = bp & (P_-1);
            const float* vb = verts + b * P_ * 3;
            float vx = vb[p*3+0], vy = vb[p*3+1], vz = vb[p*3+2];
            float sx = 0.f, sy = 0.f, sz = 0.f;
            const int* ni = nbr_idx + bp * NNB;
#pragma unroll 4
            for (int n = 0; n < NNB; n++) {
                int qq = ni[n];
                float dx = vb[qq*3+0] - vx;
                float dy = vb[qq*3+1] - vy;
                float dz = vb[qq*3+2] - vz;
                float nrm = sqrtf(dx*dx + dy*dy + dz*dz);
                float sc = 1.0f / fmaxf(nrm, 1e-12f);
                sx += dx*sc; sy += dy*sc; sz += dz*sc;
            }
            const float inv = 1.0f / (float)NNB;
            md_g[bp*3+0] = sx * inv;
            md_g[bp*3+1] = sy * inv;
            md_g[bp*3+2] = sz * inv;
        }
        if (bid == CONV_BLKS) {
            // kpo / bias_eff tables
            for (int t = tid; t < C2_*K_; t += 256) {
                int d = t / K_, k = t % K_;
                float s0 = 0.f, s1 = 0.f, s2 = 0.f;
                for (int a = 0; a < A_; a++) {
                    float w = kpw[d*36 + idx_map[k*A_ + a]];
                    s0 += w * vs[a*3+0];
                    s1 += w * vs[a*3+1];
                    s2 += w * vs[a*3+2];
                }
                float nrm = sqrtf(s0*s0 + s1*s1 + s2*s2);
                float inv = 1.0f / fmaxf(nrm, 1e-12f);
                kpo_g[t*3+0] = s0*inv;
                kpo_g[t*3+1] = s1*inv;
                kpo_g[t*3+2] = s2*inv;
            }
            for (int t = tid; t < C2_*A_; t += 256) {
                int d = t / A_, r = t % A_;
                float s = 0.f;
                for (int k = 0; k < K_; k++)
                    s += bias[d*5 + lvl[tivr[r*K_ + k]]];
                be_g[t] = s;
            }
        }
    } else {
        // ---- build_wt (bit-identical math) ----
        int u = (bid - CONV_BLKS - 64)*256 + tid;     // exact coverage
        int idx = u*2;
        int ca = idx % CA_;
        int t  = idx / CA_;
        int n  = t % DR_;
        int k  = t / DR_;
        int d = n / A_, r = n % A_;
        __nv_bfloat162 h;
        {
            int c = ca / A_, a = ca % A_;
            int j = idx_map[tivr[r*K_ + k]*A_ + tir[r*A_ + a]];
            h.x = __float2bfloat16_rn(W[(d*C1_ + c)*36 + j] * kpw[d*36 + j]);
        }
        {
            int ca2 = ca + 1;
            int c = ca2 / A_, a = ca2 % A_;
            int j = idx_map[tivr[r*K_ + k]*A_ + tir[r*A_ + a]];
            h.y = __float2bfloat16_rn(W[(d*C1_ + c)*36 + j] * kpw[d*36 + j]);
        }
        *(__nv_bfloat162*)(WTb_g + idx) = h;
    }
}

// ===================== main bf16 mma kernel (champion, verbatim) ===========
// 256 thr, warp grid 4m x 2n (warp tile 32x48), CTA tile 128x96, grid (4,128).
// CHUNK=96, 2-stage ring, issue(t+1) before compute(t), 1 sync/chunk,
// acc in regs, per-k fold -> global out (CTA-disjoint, L2-resident).
#define OFF_MD  23296
#define OFF_KPO 23680
#define OFF_BE  23992
#define SMEM_FLOATS 24088
#define SMEM_BYTES (SMEM_FLOATS*4)   /* 96352 B -> 2 CTAs/SM */

__global__ __launch_bounds__(NTHR, 2) void equi_mma(float* __restrict__ out) {
    extern __shared__ float s[];
    float* MD  = s + OFF_MD;
    float* KPO = s + OFF_KPO;
    float* BE  = s + OFF_BE;
    const uint32_t sS = smem_u32(s);

    const int tid  = threadIdx.x;
    const int wid  = tid >> 5;
    const int lane = tid & 31;
    const int gid  = lane >> 2;
    const int tig  = lane & 3;

    const int Ntile = blockIdx.x;        // 0..3
    const int Mtile = blockIdx.y;        // 0..127
    const int b  = Mtile >> 6;
    const int p0 = (Mtile & 63) << 7;
    const int n0 = Ntile * NTILE_N;
    const int d0 = Ntile * 8;

    const int m0w = (wid & 3) * 32;      // warp tile 32m x 48n
    const int n0w = (wid >> 2) * 48;

    for (int i = tid; i < 128*3; i += NTHR) MD[i]  = md_g[(size_t)Mtile*128*3 + i];
    for (int i = tid; i < 8*K_*3; i += NTHR) KPO[i] = kpo_g[d0*(K_*3) + i];
    if (tid < NTILE_N) BE[tid] = be_g[d0*A_ + tid];

    float acc[2][6][4];
#pragma unroll
    for (int mt = 0; mt < 2; mt++)
#pragma unroll
        for (int nt = 0; nt < 6; nt++)
#pragma unroll
            for (int q = 0; q < 4; q++) acc[mt][nt][q] = 0.f;

    // ---- precomputed copy offsets ----
    uint32_t aS[6], aG[6];
#pragma unroll
    for (int i = 0; i < 6; i++) {
        int o = tid + i*NTHR;
        int row = o / 12, q = o - row*12;
        aS[i] = (uint32_t)(row*SRB + q*16);
        aG[i] = (uint32_t)(row*192 + q*16);
    }
    uint32_t bS[5], bG[5];
#pragma unroll
    for (int i = 0; i < 5; i++) {
        int o = tid + i*NTHR;
        int row = o / 12, q = o - row*12;
        bS[i] = (uint32_t)(row*SRB + q*16);
        bG[i] = (uint32_t)(row*768 + q*16);
    }
    const char* fm_base  = (const char*)fmbf_g + (size_t)b*(K_*CPK*P_*192) + (size_t)p0*192;
    const char* wtb_base = (const char*)WTb_g + (size_t)n0*768;

    const uint32_t lmA = (uint32_t)((m0w + (lane & 15))*SRB + ((lane & 16) ? 16 : 0));
    const uint32_t lmB = (uint32_t)((n0w + (lane & 15))*SRB + ((lane & 16) ? 16 : 0));

    auto issue_copies = [&](int t) {
        uint32_t dstA = sS + (uint32_t)(t & 1)*STG_BY;
        uint32_t dstB = dstA + STG_A_BY;
        const char* asrc = fm_base + (size_t)t*(P_*192);
#pragma unroll
        for (int i = 0; i < 6; i++) cp16(dstA + aS[i], asrc + aG[i]);
        int k = t >> 2, j = t & 3;
        const char* bsrc = wtb_base + (size_t)k*(DR_*CA_*2) + j*192;
#pragma unroll
        for (int i = 0; i < 4; i++) cp16(dstB + bS[i], bsrc + bG[i]);
        if (tid < 128) cp16(dstB + bS[4], bsrc + bG[4]);
    };

    issue_copies(0); CP_COMMIT();

    for (int t = 0; t < TCH; t++) {
        const int k  = t >> 2;
        const int j  = t & 3;

        CP_WAIT0();            // chunk t landed
        __syncthreads();       // data visible; other buffer's readers done

        if (t + 1 < TCH) { issue_copies(t + 1); CP_COMMIT(); }

        const uint32_t Ab = sS + (uint32_t)(t & 1)*STG_BY;
        const uint32_t Bb = Ab + STG_A_BY;
#pragma unroll
        for (int kb = 0; kb < NKB; kb++) {
            const uint32_t co = (uint32_t)kb*32;
            uint32_t b0[6], b1[6];
#pragma unroll
            for (int ntp = 0; ntp < 3; ntp++) {
                uint32_t r0, r1, r2, r3;
                ldsm_x4(r0, r1, r2, r3, Bb + lmB + (uint32_t)(ntp*16*SRB) + co);
                b0[2*ntp]   = r0; b1[2*ntp]   = r2;
                b0[2*ntp+1] = r1; b1[2*ntp+1] = r3;
            }
#pragma unroll
            for (int mt = 0; mt < 2; mt++) {
                uint32_t a0, a1, a2, a3;
                ldsm_x4(a0, a1, a2, a3, Ab + lmA + (uint32_t)(mt*16*SRB) + co);
#pragma unroll
                for (int nt = 0; nt < 6; nt++)
                    mma_bf16(acc[mt][nt][0], acc[mt][nt][1], acc[mt][nt][2], acc[mt][nt][3],
                             a0, a1, a2, a3, b0[nt], b1[nt]);
            }
        }

        if (j == CPK-1) {
            // fold: out (+)= pw * acc  (CTA-disjoint; L2-resident)
#pragma unroll
            for (int mt = 0; mt < 2; mt++) {
                int r0 = m0w + mt*16 + gid;
                int r1 = r0 + 8;
                float m0x = MD[r0*3+0], m0y = MD[r0*3+1], m0z = MD[r0*3+2];
                float m1x = MD[r1*3+0], m1y = MD[r1*3+1], m1z = MD[r1*3+2];
#pragma unroll
                for (int nt = 0; nt < 6; nt++) {
                    int n  = n0w + nt*8 + tig*2;
                    int dl = n / 12;
                    int rr = n - dl*12;
                    const float* kp = KPO + (dl*K_ + k)*3;
                    float pw0 = fmaxf(m0x*kp[0] + m0y*kp[1] + m0z*kp[2], 0.f);
                    float pw1 = fmaxf(m1x*kp[0] + m1y*kp[1] + m1z*kp[2], 0.f);
                    float* o0 = out + ((size_t)(b*C2_ + d0 + dl)*P_ + p0 + r0)*A_ + rr;
                    float* o1 = out + ((size_t)(b*C2_ + d0 + dl)*P_ + p0 + r1)*A_ + rr;
                    if (k == 0) {
                        *(float2*)o0 = make_float2(pw0*acc[mt][nt][0], pw0*acc[mt][nt][1]);
                        *(float2*)o1 = make_float2(pw1*acc[mt][nt][2], pw1*acc[mt][nt][3]);
                    } else if (k == K_-1) {
                        float2 c0 = *(float2*)o0, c1 = *(float2*)o1;
                        float be0 = BE[n], be1 = BE[n+1];
                        c0.x = fmaxf(fmaf(pw0, acc[mt][nt][0], c0.x) + be0, 0.f);
                        c0.y = fmaxf(fmaf(pw0, acc[mt][nt][1], c0.y) + be1, 0.f);
                        c1.x = fmaxf(fmaf(pw1, acc[mt][nt][2], c1.x) + be0, 0.f);
                        c1.y = fmaxf(fmaf(pw1, acc[mt][nt][3], c1.y) + be1, 0.f);
                        *(float2*)o0 = c0;
                        *(float2*)o1 = c1;
                    } else {
                        float2 c0 = *(float2*)o0, c1 = *(float2*)o1;
                        c0.x = fmaf(pw0, acc[mt][nt][0], c0.x);
                        c0.y = fmaf(pw0, acc[mt][nt][1], c0.y);
                        c1.x = fmaf(pw1, acc[mt][nt][2], c1.x);
                        c1.y = fmaf(pw1, acc[mt][nt][3], c1.y);
                        *(float2*)o0 = c0;
                        *(float2*)o1 = c1;
                    }
                    acc[mt][nt][0] = 0.f; acc[mt][nt][1] = 0.f;
                    acc[mt][nt][2] = 0.f; acc[mt][nt][3] = 0.f;
                }
            }
        }
    }
}

// ---------------------------------------------------------------------------
extern "C" void kernel_launch(void* const* d_in, const int* in_sizes, int n_in,
                              void* d_out, int out_size) {
    const int*   nbr     = (const int*)  d_in[0];
    const float* verts   = (const float*)d_in[1];
    const float* fm      = (const float*)d_in[2];
    const float* W       = (const float*)d_in[3];
    const float* bias    = (const float*)d_in[4];
    const float* kpw     = (const float*)d_in[5];
    const float* vs      = (const float*)d_in[6];
    const int*   idx_map = (const int*)  d_in[7];
    const int*   tivr    = (const int*)  d_in[8];
    const int*   tir     = (const int*)  d_in[9];
    const int*   lvl     = (const int*)  d_in[10];
    float* out = (float*)d_out;

    static int smem_set = 0;
    if (!smem_set) {
        cudaFuncSetAttribute(equi_mma, cudaFuncAttributeMaxDynamicSharedMemorySize, SMEM_BYTES);
        smem_set = 1;
    }

    prep_all<<<PREP_BLKS, 256>>>(fm, nbr, verts, W, kpw, vs,
                                 idx_map, tivr, tir, bias, lvl);   // launch 0
    dim3 grid(4, 128);
    equi_mma<<<grid, NTHR, SMEM_BYTES>>>(out);                     // launch 1
}